// round 8
// baseline (speedup 1.0000x reference)
#include <cuda_runtime.h>
#include <cuda_bf16.h>

// Problem constants (fixed by the reference)
#define BATCH 16
#define MCTRL 64
#define NCTRL 64
#define DEG   3
#define LKNOT 68                // M + P + 1
#define NSPAN (LKNOT - 2*DEG)   // 62 candidate spans
#define OUTU  256
#define OUTV  256
#define U_PER 8                 // u samples per block
#define NTHR  512               // 8 u-folds x 64 cols = 512 fold tasks = 1/thread

// Fully fused kernel. Grid: (OUTU/U_PER, BATCH) = (32,16) = 512 blocks x 512.
//
//   1. Warp 0: load 68 knots, pure-shfl inclusive scan (lane l holds elements
//      l, l+32, l+64), normalize -> K[] in smem. (Nu == Nv, uspan == vspan:
//      the reference builds V from knot_u; u/v linspaces + degrees identical.)
//   2. Each thread owns ONE fold task (up = t>>6, n = t&63): compute that u's
//      span (6-step binary search) and immediately issue its 4 LDG.128
//      control-point loads; THEN compute its own sample basis (v = t&255)
//      while the loads are in flight.
//   3. Publish the block's 8 u-bases, barrier, fold into stmp rows.
//   4. Stage B: thread t evaluates v = t&255 for the 4 u's of its half
//      (h = t>>8): 4 LDS.128 + 12 FMA + 3 STG per point, 4 points/thread.
//
// Span-search correctness: the reference predicate (tv - K[s+DEG]) > 1e-8 is
// prefix-true in s (K monotone non-decreasing; fp subtract with a fixed
// minuend is monotone), so argmin-with-first-tie == prefix-count - 1. The
// binary search probes the identical fp expression -> bit-equal span.
__global__ void __launch_bounds__(NTHR) surf_kernel(const float* __restrict__ ctrl,
                                                    const float* __restrict__ knot_u,
                                                    float* __restrict__ out) {
    const int u0 = blockIdx.x * U_PER;
    const int b  = blockIdx.y;
    const int t  = threadIdx.x;

    __shared__ float  K[LKNOT];           // normalized knots
    __shared__ float4 sbu[U_PER];         // basis for this block's u samples
    __shared__ float4 stmp[U_PER][NCTRL]; // u-folded rows (8 KB)

    // ---- 1. knots + one-warp shfl scan + normalize ------------------------
    if (t < 32) {
        const float* kn = knot_u + b * LKNOT;
        const int l = t;
        float a0 = kn[l];
        float a1 = kn[l + 32];
        float a2 = (l < 4) ? kn[l + 64] : 0.f;

        #pragma unroll
        for (int off = 1; off < 32; off <<= 1) {
            const float n0 = __shfl_up_sync(0xffffffffu, a0, off);
            const float n1 = __shfl_up_sync(0xffffffffu, a1, off);
            const float n2 = __shfl_up_sync(0xffffffffu, a2, off);
            if (l >= off) { a0 += n0; a1 += n1; a2 += n2; }
        }
        const float tot0  = __shfl_sync(0xffffffffu, a0, 31);
        const float tot1  = __shfl_sync(0xffffffffu, a1, 31);
        const float cs2_3 = __shfl_sync(0xffffffffu, a2, 3);   // sum of last 4
        const float c0    = __shfl_sync(0xffffffffu, a0, 0);   // cs[0]
        const float den   = (tot0 + tot1 + cs2_3) - c0;        // cs[67]-cs[0]

        K[l]      = (a0 - c0) / den;
        K[l + 32] = (tot0 + a1 - c0) / den;
        if (l < 4) K[l + 64] = (tot0 + tot1 + a2 - c0) / den;
    }
    __syncthreads();

    // linspace(1e-5, 1-1e-5, 256): start + i*step, endpoint exact.
    const float start = 1e-5f;
    const float stop  = 1.0f - 1e-5f;
    const float step  = (stop - start) / (float)(OUTU - 1);

    // ---- 2a. fold-task span + control-point prefetch ----------------------
    const int up = t >> 6;            // 0..7
    const int n  = t & 63;            // 0..63
    const int uu = u0 + up;
    float tu = start + (float)uu * step;
    if (uu == OUTU - 1) tu = stop;

    int cu = 0;
    #pragma unroll
    for (int s = 32; s; s >>= 1) {
        const int ns = cu + s;
        if (ns <= NSPAN && ((tu - K[ns - 1 + DEG]) > 1e-8f)) cu = ns;
    }
    const int su = cu - 1;            // spanU - DEG

    const float4* cp = reinterpret_cast<const float4*>(ctrl)
                     + (size_t)b * MCTRL * NCTRL + n;
    const float4 p0 = cp[(su + 0) * NCTRL];   // in flight while we compute
    const float4 p1 = cp[(su + 1) * NCTRL];   // the own-sample basis below
    const float4 p2 = cp[(su + 2) * NCTRL];
    const float4 p3 = cp[(su + 3) * NCTRL];

    // ---- 2b. own-sample basis (v = t & 255), overlapped with the LDGs -----
    const int v = t & (OUTV - 1);
    float tv = start + (float)v * step;
    if (v == OUTV - 1) tv = stop;

    int cnt = 0;
    #pragma unroll
    for (int s = 32; s; s >>= 1) {
        const int ns = cnt + s;
        if (ns <= NSPAN && ((tv - K[ns - 1 + DEG]) > 1e-8f)) cnt = ns;
    }
    const int span = DEG + cnt - 1;

    // Cox-de Boor (mirrors the reference arithmetic, including the
    // (K1 - t) + (t - K2) denominator form).
    float Nb[DEG + 1];
    Nb[0] = 1.f;
    #pragma unroll
    for (int k = 1; k <= DEG; k++) {
        float saved = 0.f;
        #pragma unroll
        for (int r = 0; r < k; r++) {
            const float K1 = K[span + r + 1];
            const float K2 = K[span + 1 - k + r];
            const float denom = (K1 - tv) + (tv - K2);
            const float temp  = Nb[r] / denom;
            Nb[r] = saved + (K1 - tv) * temp;
            saved = (tv - K2) * temp;
        }
        Nb[k] = saved;
    }

    // ---- 3. publish block u-bases (from the low half), then fold ----------
    {
        const unsigned du = (unsigned)(t - u0);   // thread t<256 with v==t==uu
        if (du < U_PER) sbu[du] = make_float4(Nb[0], Nb[1], Nb[2], Nb[3]);
    }
    __syncthreads();

    {
        const float4 nu = sbu[up];
        float4 r;
        r.x = fmaf(nu.x, p0.x, fmaf(nu.y, p1.x, fmaf(nu.z, p2.x, nu.w * p3.x)));
        r.y = fmaf(nu.x, p0.y, fmaf(nu.y, p1.y, fmaf(nu.z, p2.y, nu.w * p3.y)));
        r.z = fmaf(nu.x, p0.z, fmaf(nu.y, p1.z, fmaf(nu.z, p2.z, nu.w * p3.z)));
        r.w = 0.f;
        stmp[up][n] = r;
    }
    __syncthreads();

    // ---- 4. Stage B: half h evaluates u's h*4 .. h*4+3 for v --------------
    const int   h   = t >> 8;              // 0 or 1
    const int   sv  = span - DEG;
    const float nv0 = Nb[0], nv1 = Nb[1], nv2 = Nb[2], nv3 = Nb[3];

    float* op = out + (((size_t)b * OUTU + (u0 + h * 4)) * OUTV + v) * 3;

    #pragma unroll
    for (int w = 0; w < 4; w++) {
        const float4 c0 = stmp[h * 4 + w][sv + 0];
        const float4 c1 = stmp[h * 4 + w][sv + 1];
        const float4 c2 = stmp[h * 4 + w][sv + 2];
        const float4 c3 = stmp[h * 4 + w][sv + 3];

        const float ax = fmaf(nv0, c0.x, fmaf(nv1, c1.x, fmaf(nv2, c2.x, nv3 * c3.x)));
        const float ay = fmaf(nv0, c0.y, fmaf(nv1, c1.y, fmaf(nv2, c2.y, nv3 * c3.y)));
        const float az = fmaf(nv0, c0.z, fmaf(nv1, c1.z, fmaf(nv2, c2.z, nv3 * c3.z)));

        float* o = op + (size_t)w * OUTV * 3;
        o[0] = ax;
        o[1] = ay;
        o[2] = az;
    }
}

// ---------------------------------------------------------------------------
// Launch. Inputs per metadata order: ctrl_pts [16,64,64,4] f32,
// knot_u [16,68] f32, knot_v [16,68] f32 (unused — the reference builds both
// directions from knot_u).
// ---------------------------------------------------------------------------
extern "C" void kernel_launch(void* const* d_in, const int* in_sizes, int n_in,
                              void* d_out, int out_size) {
    const float* ctrl   = (const float*)d_in[0];
    const float* knot_u = (const float*)d_in[1];
    float* out = (float*)d_out;

    surf_kernel<<<dim3(OUTU / U_PER, BATCH), NTHR>>>(ctrl, knot_u, out);
}

// round 9
// speedup vs baseline: 1.1212x; 1.1212x over previous
#include <cuda_runtime.h>
#include <cuda_bf16.h>

// Problem constants (fixed by the reference)
#define BATCH 16
#define MCTRL 64
#define NCTRL 64
#define DEG   3
#define LKNOT 68                // M + P + 1
#define NSPAN (LKNOT - 2*DEG)   // 62 candidate spans
#define OUTU  256
#define OUTV  256
#define U_PER 8                 // u samples per block

// Fully fused kernel. Grid: (OUTU/U_PER, BATCH) = (32,16) = 512 x 256 threads.
//
//   1. Warp 0: load 68 knots, pure-shfl inclusive scan (lane l holds elements
//      l, l+32, l+64), normalize -> K[] in smem. (Nu == Nv and uspan == vspan:
//      the reference builds V from knot_u; u/v linspaces + degrees identical.)
//   2. Each thread owns TWO fold tasks (up = t>>6 and up+4, col n = t&63):
//      compute both u-spans (6-step binary searches), immediately issue all
//      8 LDG.128 control-point prefetches, THEN compute both u-bases and the
//      own v-basis (3 Cox-de-Boors) while the loads are in flight. Fold
//      directly with in-register u-bases — no smem publish, no extra barrier.
//   3. Stage B: thread t evaluates v = t for all 8 u's:
//      4 LDS.128 + 12 FMA + 3 STG per point.
//
// Span-search correctness: the reference predicate (tv - K[s+DEG]) > 1e-8 is
// prefix-true in s (K monotone non-decreasing; fp subtract with a fixed
// minuend is monotone), so argmin-with-first-tie == prefix-count - 1. The
// binary search probes the identical fp expression -> bit-equal span.
// Cox-de Boor uses __fdividef (2-ulp): rel-err impact ~1e-6 vs 1e-3 tolerance.

__device__ __forceinline__ int find_cnt(const float* __restrict__ K, float tv) {
    int cnt = 0;
    #pragma unroll
    for (int s = 32; s; s >>= 1) {
        const int ns = cnt + s;
        if (ns <= NSPAN && ((tv - K[ns - 1 + DEG]) > 1e-8f)) cnt = ns;
    }
    return cnt;
}

__device__ __forceinline__ float4 cox_de_boor(const float* __restrict__ K,
                                              float tv, int span) {
    float Nb[DEG + 1];
    Nb[0] = 1.f;
    #pragma unroll
    for (int k = 1; k <= DEG; k++) {
        float saved = 0.f;
        #pragma unroll
        for (int r = 0; r < k; r++) {
            const float K1 = K[span + r + 1];
            const float K2 = K[span + 1 - k + r];
            const float denom = (K1 - tv) + (tv - K2);
            const float temp  = __fdividef(Nb[r], denom);
            Nb[r] = saved + (K1 - tv) * temp;
            saved = (tv - K2) * temp;
        }
        Nb[k] = saved;
    }
    return make_float4(Nb[0], Nb[1], Nb[2], Nb[3]);
}

__global__ void __launch_bounds__(256) surf_kernel(const float* __restrict__ ctrl,
                                                   const float* __restrict__ knot_u,
                                                   float* __restrict__ out) {
    const int u0 = blockIdx.x * U_PER;
    const int b  = blockIdx.y;
    const int t  = threadIdx.x;

    __shared__ float  K[LKNOT];           // normalized knots
    __shared__ float4 stmp[U_PER][NCTRL]; // u-folded rows (8 KB)

    // ---- 1. knots + one-warp shfl scan + normalize ------------------------
    if (t < 32) {
        const float* kn = knot_u + b * LKNOT;
        const int l = t;
        float a0 = kn[l];
        float a1 = kn[l + 32];
        float a2 = (l < 4) ? kn[l + 64] : 0.f;

        #pragma unroll
        for (int off = 1; off < 32; off <<= 1) {
            const float n0 = __shfl_up_sync(0xffffffffu, a0, off);
            const float n1 = __shfl_up_sync(0xffffffffu, a1, off);
            const float n2 = __shfl_up_sync(0xffffffffu, a2, off);
            if (l >= off) { a0 += n0; a1 += n1; a2 += n2; }
        }
        const float tot0  = __shfl_sync(0xffffffffu, a0, 31);
        const float tot1  = __shfl_sync(0xffffffffu, a1, 31);
        const float cs2_3 = __shfl_sync(0xffffffffu, a2, 3);   // sum of last 4
        const float c0    = __shfl_sync(0xffffffffu, a0, 0);   // cs[0]
        const float den   = (tot0 + tot1 + cs2_3) - c0;        // cs[67]-cs[0]

        K[l]      = (a0 - c0) / den;
        K[l + 32] = (tot0 + a1 - c0) / den;
        if (l < 4) K[l + 64] = (tot0 + tot1 + a2 - c0) / den;
    }
    __syncthreads();

    // linspace(1e-5, 1-1e-5, 256): start + i*step, endpoint exact.
    const float start = 1e-5f;
    const float stop  = 1.0f - 1e-5f;
    const float step  = (stop - start) / (float)(OUTU - 1);

    // ---- 2. two fold tasks: spans, prefetch, then overlapped basis math ---
    const int up = t >> 6;            // 0..3  (second task: up+4)
    const int n  = t & 63;            // 0..63
    const int uA = u0 + up;
    const int uB = u0 + up + 4;

    float tA = start + (float)uA * step;
    if (uA == OUTU - 1) tA = stop;
    float tB = start + (float)uB * step;
    if (uB == OUTU - 1) tB = stop;

    const int cA = find_cnt(K, tA);   // spanA = DEG + cA - 1
    const int cB = find_cnt(K, tB);
    const int sA = cA - 1;            // spanA - DEG
    const int sB = cB - 1;

    const float4* cp = reinterpret_cast<const float4*>(ctrl)
                     + (size_t)b * MCTRL * NCTRL + n;
    // All 8 loads in flight across the 3 Cox-de-Boor computations below.
    const float4 a0 = cp[(sA + 0) * NCTRL];
    const float4 a1 = cp[(sA + 1) * NCTRL];
    const float4 a2 = cp[(sA + 2) * NCTRL];
    const float4 a3 = cp[(sA + 3) * NCTRL];
    const float4 b0 = cp[(sB + 0) * NCTRL];
    const float4 b1 = cp[(sB + 1) * NCTRL];
    const float4 b2 = cp[(sB + 2) * NCTRL];
    const float4 b3 = cp[(sB + 3) * NCTRL];

    // Own v-basis (v == t) + the two u-bases, while the LDGs fly.
    const int v = t;
    float tv = start + (float)v * step;
    if (v == OUTV - 1) tv = stop;
    const int cv = find_cnt(K, tv);
    const int sv = cv - 1;
    const float4 Nv = cox_de_boor(K, tv, DEG + cv - 1);
    const float4 NA = cox_de_boor(K, tA, DEG + cA - 1);
    const float4 NB = cox_de_boor(K, tB, DEG + cB - 1);

    // Fold both tasks (prefetched data now resident).
    {
        float4 r;
        r.x = fmaf(NA.x, a0.x, fmaf(NA.y, a1.x, fmaf(NA.z, a2.x, NA.w * a3.x)));
        r.y = fmaf(NA.x, a0.y, fmaf(NA.y, a1.y, fmaf(NA.z, a2.y, NA.w * a3.y)));
        r.z = fmaf(NA.x, a0.z, fmaf(NA.y, a1.z, fmaf(NA.z, a2.z, NA.w * a3.z)));
        r.w = 0.f;
        stmp[up][n] = r;

        float4 s;
        s.x = fmaf(NB.x, b0.x, fmaf(NB.y, b1.x, fmaf(NB.z, b2.x, NB.w * b3.x)));
        s.y = fmaf(NB.x, b0.y, fmaf(NB.y, b1.y, fmaf(NB.z, b2.y, NB.w * b3.y)));
        s.z = fmaf(NB.x, b0.z, fmaf(NB.y, b1.z, fmaf(NB.z, b2.z, NB.w * b3.z)));
        s.w = 0.f;
        stmp[up + 4][n] = s;
    }
    __syncthreads();

    // ---- 3. Stage B: per-v contraction (v == t, basis in registers) --------
    float* op = out + (((size_t)b * OUTU + u0) * OUTV + v) * 3;

    #pragma unroll
    for (int w = 0; w < U_PER; w++) {
        const float4 c0 = stmp[w][sv + 0];
        const float4 c1 = stmp[w][sv + 1];
        const float4 c2 = stmp[w][sv + 2];
        const float4 c3 = stmp[w][sv + 3];

        const float ax = fmaf(Nv.x, c0.x, fmaf(Nv.y, c1.x, fmaf(Nv.z, c2.x, Nv.w * c3.x)));
        const float ay = fmaf(Nv.x, c0.y, fmaf(Nv.y, c1.y, fmaf(Nv.z, c2.y, Nv.w * c3.y)));
        const float az = fmaf(Nv.x, c0.z, fmaf(Nv.y, c1.z, fmaf(Nv.z, c2.z, Nv.w * c3.z)));

        float* o = op + (size_t)w * OUTV * 3;
        o[0] = ax;
        o[1] = ay;
        o[2] = az;
    }
}

// ---------------------------------------------------------------------------
// Launch. Inputs per metadata order: ctrl_pts [16,64,64,4] f32,
// knot_u [16,68] f32, knot_v [16,68] f32 (unused — the reference builds both
// directions from knot_u).
// ---------------------------------------------------------------------------
extern "C" void kernel_launch(void* const* d_in, const int* in_sizes, int n_in,
                              void* d_out, int out_size) {
    const float* ctrl   = (const float*)d_in[0];
    const float* knot_u = (const float*)d_in[1];
    float* out = (float*)d_out;

    surf_kernel<<<dim3(OUTU / U_PER, BATCH), 256>>>(ctrl, knot_u, out);
}

// round 10
// speedup vs baseline: 1.2149x; 1.0836x over previous
#include <cuda_runtime.h>
#include <cuda_bf16.h>

// Problem constants (fixed by the reference)
#define BATCH 16
#define MCTRL 64
#define NCTRL 64
#define DEG   3
#define LKNOT 68                // M + P + 1
#define NSPAN (LKNOT - 2*DEG)   // 62 candidate spans
#define OUTU  256
#define OUTV  256
#define U_PER 8                 // u samples per block

// Fully fused kernel. Grid: (OUTU/U_PER, BATCH) = (32,16) = 512 x 256 threads.
//
//   1. Warp 0: load 68 knots, pure-shfl inclusive scan (lane l holds elements
//      l, l+32, l+64), normalize -> K[] in smem. (Nu == Nv and uspan == vspan:
//      the reference builds V from knot_u; u/v linspaces + degrees identical.)
//   2. Each thread: compute its TWO fold tasks' u-spans (cheap binary
//      searches, no basis), immediately issue all 8 LDG.128 control-point
//      prefetches (MLP=8), THEN compute its own sample basis (one binary
//      search + one Cox-de-Boor) while the loads are in flight.
//   3. The 8 threads whose sample is one of the block's u's publish their
//      basis to smem; barrier; fold both tasks with the prefetched data.
//   4. Stage B: thread t evaluates v = t for all 8 u's:
//      4 LDS.128 + 12 FMA + 3 streaming STG per point.
//
// Span-search correctness: the reference predicate (tv - K[s+DEG]) > 1e-8 is
// prefix-true in s (K monotone non-decreasing; fp subtract with a fixed
// minuend is monotone), so argmin-with-first-tie == prefix-count - 1. The
// binary search probes the identical fp expression -> bit-equal span.
// Cox-de Boor uses __fdividef (2-ulp) -- ~1e-6 impact vs 1e-3 tolerance.

__device__ __forceinline__ int find_cnt(const float* __restrict__ K, float tv) {
    int cnt = 0;
    #pragma unroll
    for (int s = 32; s; s >>= 1) {
        const int ns = cnt + s;
        if (ns <= NSPAN && ((tv - K[ns - 1 + DEG]) > 1e-8f)) cnt = ns;
    }
    return cnt;
}

__global__ void __launch_bounds__(256) surf_kernel(const float* __restrict__ ctrl,
                                                   const float* __restrict__ knot_u,
                                                   float* __restrict__ out) {
    const int u0 = blockIdx.x * U_PER;
    const int b  = blockIdx.y;
    const int t  = threadIdx.x;

    __shared__ float  K[LKNOT];           // normalized knots
    __shared__ float4 sbu[U_PER];         // basis for this block's u samples
    __shared__ float4 stmp[U_PER][NCTRL]; // u-folded rows (8 KB)

    // ---- 1. knots + one-warp shfl scan + normalize ------------------------
    if (t < 32) {
        const float* kn = knot_u + b * LKNOT;
        const int l = t;
        float a0 = kn[l];
        float a1 = kn[l + 32];
        float a2 = (l < 4) ? kn[l + 64] : 0.f;

        #pragma unroll
        for (int off = 1; off < 32; off <<= 1) {
            const float n0 = __shfl_up_sync(0xffffffffu, a0, off);
            const float n1 = __shfl_up_sync(0xffffffffu, a1, off);
            const float n2 = __shfl_up_sync(0xffffffffu, a2, off);
            if (l >= off) { a0 += n0; a1 += n1; a2 += n2; }
        }
        const float tot0  = __shfl_sync(0xffffffffu, a0, 31);
        const float tot1  = __shfl_sync(0xffffffffu, a1, 31);
        const float cs2_3 = __shfl_sync(0xffffffffu, a2, 3);   // sum of last 4
        const float c0    = __shfl_sync(0xffffffffu, a0, 0);   // cs[0]
        const float den   = (tot0 + tot1 + cs2_3) - c0;        // cs[67]-cs[0]

        K[l]      = (a0 - c0) / den;
        K[l + 32] = (tot0 + a1 - c0) / den;
        if (l < 4) K[l + 64] = (tot0 + tot1 + a2 - c0) / den;
    }
    __syncthreads();

    // linspace(1e-5, 1-1e-5, 256): start + i*step, endpoint exact.
    const float start = 1e-5f;
    const float stop  = 1.0f - 1e-5f;
    const float step  = (stop - start) / (float)(OUTU - 1);

    // ---- 2a. fold-task spans (cheap) + 8-deep LDG prefetch ----------------
    const int up = t >> 6;            // 0..3  (second task: up+4)
    const int n  = t & 63;            // 0..63
    const int uA = u0 + up;
    const int uB = u0 + up + 4;

    float tA = start + (float)uA * step;
    if (uA == OUTU - 1) tA = stop;
    float tB = start + (float)uB * step;
    if (uB == OUTU - 1) tB = stop;

    const int sA = find_cnt(K, tA) - 1;    // spanA - DEG
    const int sB = find_cnt(K, tB) - 1;

    const float4* cp = reinterpret_cast<const float4*>(ctrl)
                     + (size_t)b * MCTRL * NCTRL + n;
    // All 8 loads in flight across the Cox-de-Boor math below (MLP=8).
    const float4 a0 = cp[(sA + 0) * NCTRL];
    const float4 a1 = cp[(sA + 1) * NCTRL];
    const float4 a2 = cp[(sA + 2) * NCTRL];
    const float4 a3 = cp[(sA + 3) * NCTRL];
    const float4 b0 = cp[(sB + 0) * NCTRL];
    const float4 b1 = cp[(sB + 1) * NCTRL];
    const float4 b2 = cp[(sB + 2) * NCTRL];
    const float4 b3 = cp[(sB + 3) * NCTRL];

    // ---- 2b. own-sample basis (v == t), overlapped with the LDGs ----------
    const int v = t;
    float tv = start + (float)v * step;
    if (v == OUTV - 1) tv = stop;

    const int cv   = find_cnt(K, tv);
    const int span = DEG + cv - 1;
    const int sv   = cv - 1;

    float Nb[DEG + 1];
    Nb[0] = 1.f;
    #pragma unroll
    for (int k = 1; k <= DEG; k++) {
        float saved = 0.f;
        #pragma unroll
        for (int r = 0; r < k; r++) {
            const float K1 = K[span + r + 1];
            const float K2 = K[span + 1 - k + r];
            const float denom = (K1 - tv) + (tv - K2);
            const float temp  = __fdividef(Nb[r], denom);
            Nb[r] = saved + (K1 - tv) * temp;
            saved = (tv - K2) * temp;
        }
        Nb[k] = saved;
    }

    // ---- 3. publish the block's u-bases, barrier, fold ---------------------
    {
        const unsigned du = (unsigned)(t - u0);   // thread with v == u0+du
        if (du < U_PER) sbu[du] = make_float4(Nb[0], Nb[1], Nb[2], Nb[3]);
    }
    __syncthreads();

    {
        const float4 NA = sbu[up];
        const float4 NB = sbu[up + 4];

        float4 r;
        r.x = fmaf(NA.x, a0.x, fmaf(NA.y, a1.x, fmaf(NA.z, a2.x, NA.w * a3.x)));
        r.y = fmaf(NA.x, a0.y, fmaf(NA.y, a1.y, fmaf(NA.z, a2.y, NA.w * a3.y)));
        r.z = fmaf(NA.x, a0.z, fmaf(NA.y, a1.z, fmaf(NA.z, a2.z, NA.w * a3.z)));
        r.w = 0.f;
        stmp[up][n] = r;

        float4 s;
        s.x = fmaf(NB.x, b0.x, fmaf(NB.y, b1.x, fmaf(NB.z, b2.x, NB.w * b3.x)));
        s.y = fmaf(NB.x, b0.y, fmaf(NB.y, b1.y, fmaf(NB.z, b2.y, NB.w * b3.y)));
        s.z = fmaf(NB.x, b0.z, fmaf(NB.y, b1.z, fmaf(NB.z, b2.z, NB.w * b3.z)));
        s.w = 0.f;
        stmp[up + 4][n] = s;
    }
    __syncthreads();

    // ---- 4. Stage B: per-v contraction (v == t, basis in registers) --------
    const float nv0 = Nb[0], nv1 = Nb[1], nv2 = Nb[2], nv3 = Nb[3];

    float* op = out + (((size_t)b * OUTU + u0) * OUTV + v) * 3;

    #pragma unroll
    for (int w = 0; w < U_PER; w++) {
        const float4 c0 = stmp[w][sv + 0];
        const float4 c1 = stmp[w][sv + 1];
        const float4 c2 = stmp[w][sv + 2];
        const float4 c3 = stmp[w][sv + 3];

        const float ax = fmaf(nv0, c0.x, fmaf(nv1, c1.x, fmaf(nv2, c2.x, nv3 * c3.x)));
        const float ay = fmaf(nv0, c0.y, fmaf(nv1, c1.y, fmaf(nv2, c2.y, nv3 * c3.y)));
        const float az = fmaf(nv0, c0.z, fmaf(nv1, c1.z, fmaf(nv2, c2.z, nv3 * c3.z)));

        float* o = op + (size_t)w * OUTV * 3;
        __stcs(o + 0, ax);   // streaming: write-once output, keep out of L1
        __stcs(o + 1, ay);
        __stcs(o + 2, az);
    }
}

// ---------------------------------------------------------------------------
// Launch. Inputs per metadata order: ctrl_pts [16,64,64,4] f32,
// knot_u [16,68] f32, knot_v [16,68] f32 (unused — the reference builds both
// directions from knot_u).
// ---------------------------------------------------------------------------
extern "C" void kernel_launch(void* const* d_in, const int* in_sizes, int n_in,
                              void* d_out, int out_size) {
    const float* ctrl   = (const float*)d_in[0];
    const float* knot_u = (const float*)d_in[1];
    float* out = (float*)d_out;

    surf_kernel<<<dim3(OUTU / U_PER, BATCH), 256>>>(ctrl, knot_u, out);
}